// round 3
// baseline (speedup 1.0000x reference)
#include <cuda_runtime.h>
#include <math.h>

#define NN   8192
#define DIN  512
#define DD   64
#define NEGINF -9e15f

// Scratch for projected features (device globals: no allocation allowed).
__device__ float g_kh[NN * DD];
__device__ float g_vh[NN * DD];

// ---------------------------------------------------------------------------
// Kernel A (correctness-first): one thread per output element.
// kh[r][c] = sum_k inp[r][k] * kW[k][c];  vh likewise.
// kW/vW (128KB each) are L2/L1 resident; inp row reads broadcast within block.
// ---------------------------------------------------------------------------
__global__ void __launch_bounds__(256) proj_kernel(const float* __restrict__ inp,
                                                   const float* __restrict__ kW,
                                                   const float* __restrict__ vW) {
    int idx = blockIdx.x * 256 + threadIdx.x;   // < NN*DD
    int r = idx >> 6;
    int c = idx & 63;
    const float* xrow = inp + (long)r * DIN;
    float ak = 0.f, av = 0.f;
    #pragma unroll 8
    for (int k = 0; k < DIN; k++) {
        float x = xrow[k];
        ak = fmaf(x, kW[k * DD + c], ak);
        av = fmaf(x, vW[k * DD + c], av);
    }
    g_kh[idx] = ak;
    g_vh[idx] = av;
}

// ---------------------------------------------------------------------------
// Kernel B: fused masked flash attention + ELU.
// grid = 128 (64 query rows per CTA), block = 16x16 (256 threads).
// BN = 64 keys per tile, 128 tiles. ALL reductions via shared memory with
// explicit barriers (no shuffles), no buffer aliasing, scalar fills only.
//
// smem layout (floats):
//   khq : 64*65   query kh tile (loaded once)
//   skk : 64*65   key   kh tile
//   svh : 64*68   value tile
//   Ps  : 64*68   probabilities (separate buffer!)
//   red : 64*16   per-row partial reductions (one slot per tx lane)
//   rowm: 64      running max
//   rowl: 64      running denom
//   rowf: 64      rescale factor of current tile
// ---------------------------------------------------------------------------
#define F_KHQ 0
#define F_SKK (F_KHQ + 64 * 65)
#define F_SVH (F_SKK + 64 * 65)
#define F_PS  (F_SVH + 64 * 68)
#define F_RED (F_PS  + 64 * 68)
#define F_RM  (F_RED + 64 * 16)
#define F_RL  (F_RM + 64)
#define F_RF  (F_RL + 64)
#define SMEM_B_BYTES ((F_RF + 64) * 4)

__global__ void __launch_bounds__(256, 1) attn_kernel(const int* __restrict__ adj,
                                                      float* __restrict__ out) {
    extern __shared__ float sm[];
    float* khq  = sm + F_KHQ;
    float* skk  = sm + F_SKK;
    float* svh  = sm + F_SVH;
    float* Ps   = sm + F_PS;
    float* red  = sm + F_RED;
    float* rowm = sm + F_RM;
    float* rowl = sm + F_RL;
    float* rowf = sm + F_RF;

    const int tx = threadIdx.x, ty = threadIdx.y;
    const int tid = ty * 16 + tx;
    const int qbase = blockIdx.x * 64;

    // Load query tile; init row state.
    for (int e = tid; e < 64 * 64; e += 256) {
        int r = e >> 6, c = e & 63;
        khq[r * 65 + c] = g_kh[(qbase + r) * DD + c];
    }
    if (tid < 64) { rowm[tid] = NEGINF; rowl[tid] = 0.f; }

    float o[4][4] = {};

    for (int t = 0; t < NN / 64; t++) {
        const int kbase = t * 64;
        __syncthreads();                                   // S1

        // Fill key/value tiles (scalar, coalesced).
        for (int e = tid; e < 64 * 64; e += 256) {
            int r = e >> 6, c = e & 63;
            skk[r * 65 + c] = g_kh[(kbase + r) * DD + c];
            svh[r * 68 + c] = g_vh[(kbase + r) * DD + c];
        }

        // adj entries for this thread's 4x4 score tile -> registers.
        int am[4][4];
        #pragma unroll
        for (int i = 0; i < 4; i++) {
            const int* arow = adj + (long)(qbase + ty + 16 * i) * NN + kbase;
            #pragma unroll
            for (int j = 0; j < 4; j++) am[i][j] = arow[tx + 16 * j];
        }
        __syncthreads();                                   // S2

        // S = khq @ skk^T (4x4 register tile), then mask + scale.
        float s[4][4] = {};
        #pragma unroll 8
        for (int k = 0; k < 64; k++) {
            float a[4], b[4];
            #pragma unroll
            for (int i = 0; i < 4; i++) a[i] = khq[(ty + 16 * i) * 65 + k];
            #pragma unroll
            for (int j = 0; j < 4; j++) b[j] = skk[(tx + 16 * j) * 65 + k];
            #pragma unroll
            for (int i = 0; i < 4; i++)
                #pragma unroll
                for (int j = 0; j < 4; j++)
                    s[i][j] = fmaf(a[i], b[j], s[i][j]);
        }
        #pragma unroll
        for (int i = 0; i < 4; i++) {
            float pm = NEGINF;
            #pragma unroll
            for (int j = 0; j < 4; j++) {
                s[i][j] = (am[i][j] > 0) ? s[i][j] * 0.125f : NEGINF;
                pm = fmaxf(pm, s[i][j]);
            }
            red[(ty + 16 * i) * 16 + tx] = pm;             // partial max
        }
        __syncthreads();                                   // S3

        // Phase 1 (one thread per row): new max + rescale factor.
        if (tid < 64) {
            float mm = NEGINF;
            #pragma unroll
            for (int x = 0; x < 16; x++) mm = fmaxf(mm, red[tid * 16 + x]);
            float mo = rowm[tid];
            float mn = fmaxf(mo, mm);
            rowf[tid] = __expf(mo - mn);
            rowm[tid] = mn;
        }
        __syncthreads();                                   // S4

        // Phase 2: p = exp(s - m_new); stage Ps; rescale o; partial sums.
        #pragma unroll
        for (int i = 0; i < 4; i++) {
            int row = ty + 16 * i;
            float mn = rowm[row];
            float f  = rowf[row];
            float ps = 0.f;
            #pragma unroll
            for (int j = 0; j < 4; j++) {
                float p = __expf(s[i][j] - mn);
                Ps[row * 68 + tx + 16 * j] = p;
                ps += p;
            }
            red[row * 16 + tx] = ps;                       // partial sum
            #pragma unroll
            for (int j = 0; j < 4; j++) o[i][j] *= f;
        }
        __syncthreads();                                   // S5

        // Phase 3 (one thread per row): denominator update.
        if (tid < 64) {
            float rs = 0.f;
            #pragma unroll
            for (int x = 0; x < 16; x++) rs += red[tid * 16 + x];
            rowl[tid] = rowl[tid] * rowf[tid] + rs;
        }

        // PV: O += P @ vh (Ps and svh were complete before S5).
        #pragma unroll 4
        for (int c = 0; c < 64; c++) {
            float p[4], v[4];
            #pragma unroll
            for (int i = 0; i < 4; i++) p[i] = Ps[(ty + 16 * i) * 68 + c];
            #pragma unroll
            for (int j = 0; j < 4; j++) v[j] = svh[c * 68 + tx + 16 * j];
            #pragma unroll
            for (int i = 0; i < 4; i++)
                #pragma unroll
                for (int j = 0; j < 4; j++)
                    o[i][j] = fmaf(p[i], v[j], o[i][j]);
        }
    }

    __syncthreads();   // rowl final values visible

    // Normalize + ELU + store.
    #pragma unroll
    for (int i = 0; i < 4; i++) {
        int row = ty + 16 * i;
        float inv = 1.f / rowl[row];
        #pragma unroll
        for (int j = 0; j < 4; j++) {
            float x = o[i][j] * inv;
            x = (x > 0.f) ? x : expm1f(x);
            out[(qbase + row) * DD + tx + 16 * j] = x;
        }
    }
}

namespace {
struct AttrInit {
    AttrInit() {
        cudaFuncSetAttribute(attn_kernel,
                             cudaFuncAttributeMaxDynamicSharedMemorySize,
                             SMEM_B_BYTES);
    }
} attr_init_;
}

extern "C" void kernel_launch(void* const* d_in, const int* in_sizes, int n_in,
                              void* d_out, int out_size) {
    // Bind inputs by SIZE (robust to metadata ordering):
    //   input: 8192*512 f32; adj: 8192*8192 i32; kW,vW: 512*64 f32 (kW first).
    const float* inp = nullptr;
    const int*   adj = nullptr;
    const float* kW  = nullptr;
    const float* vW  = nullptr;
    for (int i = 0; i < n_in; i++) {
        long sz = in_sizes[i];
        if (sz == (long)NN * DIN)      inp = (const float*)d_in[i];
        else if (sz == (long)NN * NN)  adj = (const int*)d_in[i];
        else if (sz == (long)DIN * DD) { if (!kW) kW = (const float*)d_in[i];
                                         else     vW = (const float*)d_in[i]; }
    }
    float* out = (float*)d_out;

    proj_kernel<<<(NN * DD) / 256, 256>>>(inp, kW, vW);
    dim3 blk(16, 16);
    attn_kernel<<<NN / 64, blk, SMEM_B_BYTES>>>(adj, out);
}